// round 10
// baseline (speedup 1.0000x reference)
#include <cuda_runtime.h>
#include <cuda_bf16.h>
#include <mma.h>
#include <math.h>
#include <cstdint>

using namespace nvcuda;

#define B_SZ   1024
#define DETER  4096
#define STOCH  1024
#define ACT    128
#define HID    1024
#define NBLK   8
#define DPB    512
#define INCH0  3584   /* 3*HID + DPB */

// ---------------- scratch (static device globals; no allocation) ----------------
__device__ __nv_bfloat16 g_w0 [DETER*HID];
__device__ __nv_bfloat16 g_w1 [STOCH*HID];
__device__ __nv_bfloat16 g_w2 [ACT*HID];
__device__ __nv_bfloat16 g_hw0[NBLK*INCH0*DPB];
__device__ __nv_bfloat16 g_hw1[NBLK*DPB*DPB];
__device__ __nv_bfloat16 g_gw [NBLK*DPB*3*DPB];
__device__ __nv_bfloat16 g_deter_bf[B_SZ*DETER];
__device__ __nv_bfloat16 g_stoch_bf[B_SZ*STOCH];
__device__ __nv_bfloat16 g_act_bf [B_SZ*ACT];
__device__ float         g_y [B_SZ*3*HID];
__device__ __nv_bfloat16 g_x [B_SZ*3*HID];
__device__ float         g_h0pre[B_SZ*DETER];
__device__ __nv_bfloat16 g_h0   [B_SZ*DETER];
__device__ float         g_h1pre[B_SZ*DETER];
__device__ __nv_bfloat16 g_h1   [B_SZ*DETER];
__device__ float         g_gpre [B_SZ*3*DETER];

// ---------------- cp.async helpers ----------------
__device__ __forceinline__ void cp_async16(void* smem, const void* gmem)
{
    unsigned int s = (unsigned int)__cvta_generic_to_shared(smem);
    asm volatile("cp.async.cg.shared.global [%0], [%1], 16;\n" :: "r"(s), "l"(gmem));
}
__device__ __forceinline__ void cp_commit() { asm volatile("cp.async.commit_group;\n"); }
template<int N> __device__ __forceinline__ void cp_wait() { asm volatile("cp.async.wait_group %0;\n" :: "n"(N)); }

// =====================================================================
// ONE conversion kernel for all weights + activations.
// =====================================================================
#define CB_W0    4096
#define CB_W1    (CB_W0 + 1024)     /* 5120 */
#define CB_W2    (CB_W1 + 128)      /* 5248 */
#define CB_HW0   (CB_W2 + 14336)    /* 19584 */
#define CB_HW1   (CB_HW0 + 2048)    /* 21632 */
#define CB_GW    (CB_HW1 + 6144)    /* 27776 */
#define CB_DET   (CB_GW + 4096)     /* 31872 */
#define CB_STO   (CB_DET + 1024)    /* 32896 */
#define CB_ACT   (CB_STO + 128)     /* 33024 */

__global__ void __launch_bounds__(256)
convall_kernel(const float* __restrict__ w0, const float* __restrict__ w1,
               const float* __restrict__ w2, const float* __restrict__ hw0,
               const float* __restrict__ hw1, const float* __restrict__ gw,
               const float* __restrict__ deter, const float* __restrict__ stoch,
               const float* __restrict__ action,
               __nv_bfloat16* o_w0, __nv_bfloat16* o_w1, __nv_bfloat16* o_w2,
               __nv_bfloat16* o_hw0, __nv_bfloat16* o_hw1, __nv_bfloat16* o_gw,
               __nv_bfloat16* o_det, __nv_bfloat16* o_sto, __nv_bfloat16* o_act)
{
    const int b = blockIdx.x;
    const float* src; __nv_bfloat16* dst; int base; bool is_act = false;
    if      (b < CB_W0)  { src = w0;    dst = o_w0;  base = b; }
    else if (b < CB_W1)  { src = w1;    dst = o_w1;  base = b - CB_W0; }
    else if (b < CB_W2)  { src = w2;    dst = o_w2;  base = b - CB_W1; }
    else if (b < CB_HW0) { src = hw0;   dst = o_hw0; base = b - CB_W2; }
    else if (b < CB_HW1) { src = hw1;   dst = o_hw1; base = b - CB_HW0; }
    else if (b < CB_GW)  { src = gw;    dst = o_gw;  base = b - CB_HW1; }
    else if (b < CB_DET) { src = deter; dst = o_det; base = b - CB_GW; }
    else if (b < CB_STO) { src = stoch; dst = o_sto; base = b - CB_DET; }
    else                 { src = action; dst = o_act; base = b - CB_STO; is_act = true; }

    int i = base * 256 + threadIdx.x;          // float4 index
    float4 t = ((const float4*)src)[i];
    if (is_act) {
        t.x /= fmaxf(fabsf(t.x), 1.0f);
        t.y /= fmaxf(fabsf(t.y), 1.0f);
        t.z /= fmaxf(fabsf(t.z), 1.0f);
        t.w /= fmaxf(fabsf(t.w), 1.0f);
    }
    ((__nv_bfloat162*)dst)[2*i]   = __floats2bfloat162_rn(t.x, t.y);
    ((__nv_bfloat162*)dst)[2*i+1] = __floats2bfloat162_rn(t.z, t.w);
}

// =====================================================================
// Double-buffered bf16 GEMM (wmma + cp.async), split-A capable.
// =====================================================================
template<int BM>
__global__ void __launch_bounds__(256)
gemm_bd_kernel(const __nv_bfloat16* __restrict__ A0, int lda0, long long a0_zs,
               const __nv_bfloat16* __restrict__ A1, int lda1, int k0, int K,
               const __nv_bfloat16* __restrict__ Bp, int ldb, long long b_zs,
               float* __restrict__ C, int ldc, long long c_zs)
{
    constexpr int BN = 128, BK = 32;
    constexpr int FM = BM / 32;
    __shared__ __nv_bfloat16 sA[2][BM][BK + 8];
    __shared__ __nv_bfloat16 sB[2][BK][BN + 8];

    const int z = blockIdx.z;
    const __nv_bfloat16* A0z = A0 + (long long)z * a0_zs;
    const __nv_bfloat16* Bz  = Bp + (long long)z * b_zs;
    float* Cz = C + (long long)z * c_zs;

    const int tile_m = blockIdx.x * BM;
    const int tile_n = blockIdx.y * BN;
    const int tid  = threadIdx.x;
    const int warp = tid >> 5;
    const int wm   = warp & 1;
    const int wn   = warp >> 1;

    auto issue = [&](int kk, int stg) {
        const __nv_bfloat16* Asrc; int lda, kcol;
        if (kk < k0) { Asrc = A0z; lda = lda0; kcol = kk; }
        else         { Asrc = A1;  lda = lda1; kcol = kk - k0; }
#pragma unroll
        for (int i = 0; i < BM / 64; i++) {
            int idx = tid + 256 * i;
            int r = idx >> 2, v = idx & 3;
            cp_async16(&sA[stg][r][v * 8],
                       Asrc + (long long)(tile_m + r) * lda + kcol + v * 8);
        }
#pragma unroll
        for (int i = 0; i < 2; i++) {
            int idx = tid + 256 * i;
            int r = idx >> 4, c = (idx & 15) * 8;
            cp_async16(&sB[stg][r][c],
                       Bz + (long long)(kk + r) * ldb + tile_n + c);
        }
    };

    wmma::fragment<wmma::accumulator, 16, 16, 16, float> acc[FM][2];
#pragma unroll
    for (int i = 0; i < FM; i++)
#pragma unroll
        for (int j = 0; j < 2; j++) wmma::fill_fragment(acc[i][j], 0.0f);

    const int nsteps = K / BK;
    issue(0, 0); cp_commit();

    for (int s = 0; s < nsteps; s++) {
        if (s + 1 < nsteps) { issue((s + 1) * BK, (s + 1) & 1); cp_commit(); cp_wait<1>(); }
        else                { cp_wait<0>(); }
        __syncthreads();
        const int stg = s & 1;
#pragma unroll
        for (int kf = 0; kf < 2; kf++) {
            wmma::fragment<wmma::matrix_a, 16, 16, 16, __nv_bfloat16, wmma::row_major> af[FM];
            wmma::fragment<wmma::matrix_b, 16, 16, 16, __nv_bfloat16, wmma::row_major> bf[2];
#pragma unroll
            for (int i = 0; i < FM; i++)
                wmma::load_matrix_sync(af[i], &sA[stg][wm * (BM / 2) + i * 16][kf * 16], BK + 8);
#pragma unroll
            for (int j = 0; j < 2; j++)
                wmma::load_matrix_sync(bf[j], &sB[stg][kf * 16][wn * 32 + j * 16], BN + 8);
#pragma unroll
            for (int i = 0; i < FM; i++)
#pragma unroll
                for (int j = 0; j < 2; j++)
                    wmma::mma_sync(acc[i][j], af[i], bf[j], acc[i][j]);
        }
        __syncthreads();
    }
#pragma unroll
    for (int i = 0; i < FM; i++)
#pragma unroll
        for (int j = 0; j < 2; j++) {
            float* cp = Cz + (long long)(tile_m + wm * (BM / 2) + i * 16) * ldc
                           + tile_n + wn * 32 + j * 16;
            wmma::store_matrix_sync(cp, acc[i][j], ldc, wmma::mem_row_major);
        }
}

// =====================================================================
// Fused 3-branch input GEMM (BM=64, BN=128, BK=32); grid (B/64, 24)
// =====================================================================
__global__ void __launch_bounds__(256)
gemm_branch_kernel(const __nv_bfloat16* __restrict__ Ad,
                   const __nv_bfloat16* __restrict__ As,
                   const __nv_bfloat16* __restrict__ Aa,
                   const __nv_bfloat16* __restrict__ W0p,
                   const __nv_bfloat16* __restrict__ W1p,
                   const __nv_bfloat16* __restrict__ W2p,
                   float* __restrict__ Y)
{
    constexpr int BM = 64, BN = 128, BK = 32;
    constexpr int FM = 2;
    __shared__ __nv_bfloat16 sA[2][BM][BK + 8];
    __shared__ __nv_bfloat16 sB[2][BK][BN + 8];

    const int br = blockIdx.y >> 3;
    const int tile_n_local = (blockIdx.y & 7) * BN;
    const __nv_bfloat16* A = (br == 0) ? Ad : (br == 1) ? As : Aa;
    const __nv_bfloat16* W = (br == 0) ? W0p : (br == 1) ? W1p : W2p;
    const int K = (br == 0) ? DETER : (br == 1) ? STOCH : ACT;
    const int lda = K;

    const int tile_m = blockIdx.x * BM;
    const int tid  = threadIdx.x;
    const int warp = tid >> 5;
    const int wm   = warp & 1;
    const int wn   = warp >> 1;

    auto issue = [&](int kk, int stg) {
        {
            int r = tid >> 2, v = tid & 3;
            cp_async16(&sA[stg][r][v * 8], A + (long long)(tile_m + r) * lda + kk + v * 8);
        }
#pragma unroll
        for (int i = 0; i < 2; i++) {
            int idx = tid + 256 * i;
            int r = idx >> 4, c = (idx & 15) * 8;
            cp_async16(&sB[stg][r][c], W + (long long)(kk + r) * HID + tile_n_local + c);
        }
    };

    wmma::fragment<wmma::accumulator, 16, 16, 16, float> acc[FM][2];
#pragma unroll
    for (int i = 0; i < FM; i++)
#pragma unroll
        for (int j = 0; j < 2; j++) wmma::fill_fragment(acc[i][j], 0.0f);

    const int nsteps = K / BK;
    issue(0, 0); cp_commit();

    for (int s = 0; s < nsteps; s++) {
        if (s + 1 < nsteps) { issue((s + 1) * BK, (s + 1) & 1); cp_commit(); cp_wait<1>(); }
        else                { cp_wait<0>(); }
        __syncthreads();
        const int stg = s & 1;
#pragma unroll
        for (int kf = 0; kf < 2; kf++) {
            wmma::fragment<wmma::matrix_a, 16, 16, 16, __nv_bfloat16, wmma::row_major> af[FM];
            wmma::fragment<wmma::matrix_b, 16, 16, 16, __nv_bfloat16, wmma::row_major> bf[2];
#pragma unroll
            for (int i = 0; i < FM; i++)
                wmma::load_matrix_sync(af[i], &sA[stg][wm * 32 + i * 16][kf * 16], BK + 8);
#pragma unroll
            for (int j = 0; j < 2; j++)
                wmma::load_matrix_sync(bf[j], &sB[stg][kf * 16][wn * 32 + j * 16], BN + 8);
#pragma unroll
            for (int i = 0; i < FM; i++)
#pragma unroll
                for (int j = 0; j < 2; j++)
                    wmma::mma_sync(acc[i][j], af[i], bf[j], acc[i][j]);
        }
        __syncthreads();
    }
#pragma unroll
    for (int i = 0; i < FM; i++)
#pragma unroll
        for (int j = 0; j < 2; j++) {
            float* cp = Y + (long long)(tile_m + wm * 32 + i * 16) * (3 * HID)
                          + br * HID + tile_n_local + wn * 32 + j * 16;
            wmma::store_matrix_sync(cp, acc[i][j], 3 * HID, wmma::mem_row_major);
        }
}

// ---------------- fused bias + RMSNorm + gain + SiLU -> bf16 ----------------
__global__ void __launch_bounds__(256)
norm_silu_kernel(const float* __restrict__ Y, int ldy,
                 const float* __restrict__ bias, const float* __restrict__ gain,
                 __nv_bfloat16* __restrict__ outp, int ldo, int W)
{
    const int row = blockIdx.x;
    const int tid = threadIdx.x;
    const int nv  = W >> 10;
    const float* yr = Y + (long long)row * ldy;

    float v[16];
    float ss = 0.0f;
#pragma unroll
    for (int i = 0; i < 4; i++) {
        if (i >= nv) break;
        int c = (tid + (i << 8)) << 2;
        float4 t  = *(const float4*)(yr + c);
        float4 bb = *(const float4*)(bias + c);
        t.x += bb.x; t.y += bb.y; t.z += bb.z; t.w += bb.w;
        v[4*i+0]=t.x; v[4*i+1]=t.y; v[4*i+2]=t.z; v[4*i+3]=t.w;
        ss += t.x*t.x + t.y*t.y + t.z*t.z + t.w*t.w;
    }
#pragma unroll
    for (int o = 16; o > 0; o >>= 1) ss += __shfl_xor_sync(0xffffffffu, ss, o);
    __shared__ float red[8];
    if ((tid & 31) == 0) red[tid >> 5] = ss;
    __syncthreads();
    float tot = 0.0f;
#pragma unroll
    for (int i = 0; i < 8; i++) tot += red[i];
    const float scale = rsqrtf(tot / (float)W + 1e-4f);

    __nv_bfloat16* orow = outp + (long long)row * ldo;
#pragma unroll
    for (int i = 0; i < 4; i++) {
        if (i >= nv) break;
        int c = (tid + (i << 8)) << 2;
        float4 gg = *(const float4*)(gain + c);
        float t0 = v[4*i+0]*scale*gg.x, t1 = v[4*i+1]*scale*gg.y;
        float t2 = v[4*i+2]*scale*gg.z, t3 = v[4*i+3]*scale*gg.w;
        float s0 = t0 / (1.0f + expf(-t0));
        float s1 = t1 / (1.0f + expf(-t1));
        float s2 = t2 / (1.0f + expf(-t2));
        float s3 = t3 / (1.0f + expf(-t3));
        *((__nv_bfloat162*)(orow + c))     = __floats2bfloat162_rn(s0, s1);
        *((__nv_bfloat162*)(orow + c) + 1) = __floats2bfloat162_rn(s2, s3);
    }
}

// 3-branch norm (W = HID), grid (B, 3)
__global__ void __launch_bounds__(256)
norm3_kernel(const float* __restrict__ Y,
             const float* __restrict__ b0, const float* __restrict__ g0,
             const float* __restrict__ b1, const float* __restrict__ g1,
             const float* __restrict__ b2, const float* __restrict__ g2,
             __nv_bfloat16* __restrict__ outp)
{
    const int row = blockIdx.x;
    const int br  = blockIdx.y;
    const int tid = threadIdx.x;
    const float* bias = (br == 0) ? b0 : (br == 1) ? b1 : b2;
    const float* gain = (br == 0) ? g0 : (br == 1) ? g1 : g2;
    const float* yr = Y + (long long)row * (3 * HID) + br * HID;

    int c = tid << 2;
    float4 t  = *(const float4*)(yr + c);
    float4 bb = *(const float4*)(bias + c);
    t.x += bb.x; t.y += bb.y; t.z += bb.z; t.w += bb.w;
    float ss = t.x*t.x + t.y*t.y + t.z*t.z + t.w*t.w;
#pragma unroll
    for (int o = 16; o > 0; o >>= 1) ss += __shfl_xor_sync(0xffffffffu, ss, o);
    __shared__ float red[8];
    if ((tid & 31) == 0) red[tid >> 5] = ss;
    __syncthreads();
    float tot = 0.0f;
#pragma unroll
    for (int i = 0; i < 8; i++) tot += red[i];
    const float scale = rsqrtf(tot / (float)HID + 1e-4f);

    float4 gg = *(const float4*)(gain + c);
    float t0 = t.x*scale*gg.x, t1 = t.y*scale*gg.y;
    float t2 = t.z*scale*gg.z, t3 = t.w*scale*gg.w;
    float s0 = t0 / (1.0f + expf(-t0));
    float s1 = t1 / (1.0f + expf(-t1));
    float s2 = t2 / (1.0f + expf(-t2));
    float s3 = t3 / (1.0f + expf(-t3));
    __nv_bfloat16* orow = outp + (long long)row * (3 * HID) + br * HID;
    *((__nv_bfloat162*)(orow + c))     = __floats2bfloat162_rn(s0, s1);
    *((__nv_bfloat162*)(orow + c) + 1) = __floats2bfloat162_rn(s2, s3);
}

// ---------------- GRU gate epilogue ----------------
__global__ void __launch_bounds__(256)
gru_kernel(const float* __restrict__ gpre, const float* __restrict__ gb,
           const float* __restrict__ deter, float* __restrict__ out)
{
    int i = blockIdx.x * blockDim.x + threadIdx.x;
    int b  = i >> 10;
    int jv = i & 1023;
    int j  = jv << 2;
    int blk = j >> 9;
    int o   = j & 511;
    const float* gp  = gpre + (long long)b * (3 * DETER) + blk * (3 * DPB);
    const float* gbp = gb + blk * (3 * DPB);
    float4 r4 = *(const float4*)(gp + o);
    float4 rb = *(const float4*)(gbp + o);
    float4 c4 = *(const float4*)(gp + DPB + o);
    float4 cb = *(const float4*)(gbp + DPB + o);
    float4 u4 = *(const float4*)(gp + 2 * DPB + o);
    float4 ub = *(const float4*)(gbp + 2 * DPB + o);
    float4 d4 = *(const float4*)(deter + (long long)b * DETER + j);

    float4 res;
    {
        float rr = 1.0f / (1.0f + expf(-(r4.x + rb.x)));
        float cc = tanhf(rr * (c4.x + cb.x));
        float uu = 1.0f / (1.0f + expf(-(u4.x + ub.x - 1.0f)));
        res.x = uu * cc + (1.0f - uu) * d4.x;
    }
    {
        float rr = 1.0f / (1.0f + expf(-(r4.y + rb.y)));
        float cc = tanhf(rr * (c4.y + cb.y));
        float uu = 1.0f / (1.0f + expf(-(u4.y + ub.y - 1.0f)));
        res.y = uu * cc + (1.0f - uu) * d4.y;
    }
    {
        float rr = 1.0f / (1.0f + expf(-(r4.z + rb.z)));
        float cc = tanhf(rr * (c4.z + cb.z));
        float uu = 1.0f / (1.0f + expf(-(u4.z + ub.z - 1.0f)));
        res.z = uu * cc + (1.0f - uu) * d4.z;
    }
    {
        float rr = 1.0f / (1.0f + expf(-(r4.w + rb.w)));
        float cc = tanhf(rr * (c4.w + cb.w));
        float uu = 1.0f / (1.0f + expf(-(u4.w + ub.w - 1.0f)));
        res.w = uu * cc + (1.0f - uu) * d4.w;
    }
    *(float4*)(out + (long long)b * DETER + j) = res;
}

// ---------------- host ----------------
extern "C" void kernel_launch(void* const* d_in, const int* in_sizes, int n_in,
                              void* d_out, int out_size)
{
    (void)in_sizes; (void)n_in; (void)out_size;
    const float* stoch  = (const float*)d_in[0];
    const float* deter  = (const float*)d_in[1];
    const float* action = (const float*)d_in[2];
    const float* w0 = (const float*)d_in[3];
    const float* b0 = (const float*)d_in[4];
    const float* g0 = (const float*)d_in[5];
    const float* w1 = (const float*)d_in[6];
    const float* b1 = (const float*)d_in[7];
    const float* g1 = (const float*)d_in[8];
    const float* w2 = (const float*)d_in[9];
    const float* b2 = (const float*)d_in[10];
    const float* g2 = (const float*)d_in[11];
    const float* hw0 = (const float*)d_in[12];
    const float* hb0 = (const float*)d_in[13];
    const float* hg0 = (const float*)d_in[14];
    const float* hw1 = (const float*)d_in[15];
    const float* hb1 = (const float*)d_in[16];
    const float* hg1 = (const float*)d_in[17];
    const float* gw  = (const float*)d_in[18];
    const float* gb  = (const float*)d_in[19];
    float* out = (float*)d_out;

    void *p_w0, *p_w1, *p_w2, *p_hw0, *p_hw1, *p_gw;
    void *p_deter, *p_stoch, *p_act, *p_y, *p_x, *p_h0pre, *p_h0, *p_h1pre, *p_h1, *p_gpre;
    cudaGetSymbolAddress(&p_w0, g_w0);
    cudaGetSymbolAddress(&p_w1, g_w1);
    cudaGetSymbolAddress(&p_w2, g_w2);
    cudaGetSymbolAddress(&p_hw0, g_hw0);
    cudaGetSymbolAddress(&p_hw1, g_hw1);
    cudaGetSymbolAddress(&p_gw, g_gw);
    cudaGetSymbolAddress(&p_deter, g_deter_bf);
    cudaGetSymbolAddress(&p_stoch, g_stoch_bf);
    cudaGetSymbolAddress(&p_act, g_act_bf);
    cudaGetSymbolAddress(&p_y, g_y);
    cudaGetSymbolAddress(&p_x, g_x);
    cudaGetSymbolAddress(&p_h0pre, g_h0pre);
    cudaGetSymbolAddress(&p_h0, g_h0);
    cudaGetSymbolAddress(&p_h1pre, g_h1pre);
    cudaGetSymbolAddress(&p_h1, g_h1);
    cudaGetSymbolAddress(&p_gpre, g_gpre);

    // --- single fused conversion launch (33024 blocks) ---
    convall_kernel<<<CB_ACT, 256>>>(w0, w1, w2, hw0, hw1, gw, deter, stoch, action,
                                    (__nv_bfloat16*)p_w0, (__nv_bfloat16*)p_w1,
                                    (__nv_bfloat16*)p_w2, (__nv_bfloat16*)p_hw0,
                                    (__nv_bfloat16*)p_hw1, (__nv_bfloat16*)p_gw,
                                    (__nv_bfloat16*)p_deter, (__nv_bfloat16*)p_stoch,
                                    (__nv_bfloat16*)p_act);

    // --- fused branch GEMMs ---
    {
        dim3 grid(B_SZ / 64, 24, 1);
        gemm_branch_kernel<<<grid, 256>>>((const __nv_bfloat16*)p_deter,
                                          (const __nv_bfloat16*)p_stoch,
                                          (const __nv_bfloat16*)p_act,
                                          (const __nv_bfloat16*)p_w0,
                                          (const __nv_bfloat16*)p_w1,
                                          (const __nv_bfloat16*)p_w2,
                                          (float*)p_y);
    }
    // branch norms -> x (bf16, [B, 3*HID])
    {
        dim3 grid(B_SZ, 3, 1);
        norm3_kernel<<<grid, 256>>>((const float*)p_y, b0, g0, b1, g1, b2, g2,
                                    (__nv_bfloat16*)p_x);
    }

    // --- hidden block layer 0: split A = [deter_block(512) | x(3072)] ---
    {
        dim3 grid(B_SZ / 64, DPB / 128, NBLK);
        gemm_bd_kernel<64><<<grid, 256>>>((const __nv_bfloat16*)p_deter, DETER, DPB,
                                          (const __nv_bfloat16*)p_x, 3 * HID, DPB, INCH0,
                                          (const __nv_bfloat16*)p_hw0, DPB, (long long)INCH0 * DPB,
                                          (float*)p_h0pre, DETER, DPB);
    }
    norm_silu_kernel<<<B_SZ, 256>>>((const float*)p_h0pre, DETER, hb0, hg0,
                                    (__nv_bfloat16*)p_h0, DETER, DETER);

    // --- hidden block layer 1 ---
    {
        dim3 grid(B_SZ / 64, DPB / 128, NBLK);
        gemm_bd_kernel<64><<<grid, 256>>>((const __nv_bfloat16*)p_h0, DETER, DPB,
                                          nullptr, 0, DPB, DPB,
                                          (const __nv_bfloat16*)p_hw1, DPB, (long long)DPB * DPB,
                                          (float*)p_h1pre, DETER, DPB);
    }
    norm_silu_kernel<<<B_SZ, 256>>>((const float*)p_h1pre, DETER, hb1, hg1,
                                    (__nv_bfloat16*)p_h1, DETER, DETER);

    // --- gate GEMM: per block [1024,512] @ [512,1536] ---
    {
        dim3 grid(B_SZ / 64, (3 * DPB) / 128, NBLK);
        gemm_bd_kernel<64><<<grid, 256>>>((const __nv_bfloat16*)p_h1, DETER, DPB,
                                          nullptr, 0, DPB, DPB,
                                          (const __nv_bfloat16*)p_gw, 3 * DPB, (long long)DPB * 3 * DPB,
                                          (float*)p_gpre, 3 * DETER, 3 * DPB);
    }

    // --- GRU epilogue ---
    {
        int nvec = (B_SZ * DETER) >> 2;
        gru_kernel<<<nvec / 256, 256>>>((const float*)p_gpre, gb, deter, out);
    }
}

// round 12
// speedup vs baseline: 1.1796x; 1.1796x over previous
#include <cuda_runtime.h>
#include <cuda_bf16.h>
#include <mma.h>
#include <math.h>
#include <cstdint>

using namespace nvcuda;

#define B_SZ   1024
#define DETER  4096
#define STOCH  1024
#define ACT    128
#define HID    1024
#define NBLK   8
#define DPB    512
#define INCH0  3584   /* 3*HID + DPB */

// ---------------- scratch (static device globals; no allocation) ----------------
__device__ __nv_bfloat16 g_w0 [DETER*HID];
__device__ __nv_bfloat16 g_w1 [STOCH*HID];
__device__ __nv_bfloat16 g_w2 [ACT*HID];
__device__ __nv_bfloat16 g_hw0[NBLK*INCH0*DPB];
__device__ __nv_bfloat16 g_hw1[NBLK*DPB*DPB];
__device__ __nv_bfloat16 g_gw [NBLK*DPB*3*DPB];
__device__ __nv_bfloat16 g_deter_bf[B_SZ*DETER];
__device__ __nv_bfloat16 g_stoch_bf[B_SZ*STOCH];
__device__ __nv_bfloat16 g_act_bf [B_SZ*ACT];
__device__ float         g_y [B_SZ*3*HID];
__device__ __nv_bfloat16 g_x [B_SZ*3*HID];
__device__ float         g_h0pre[B_SZ*DETER];
__device__ __nv_bfloat16 g_h0   [B_SZ*DETER];
__device__ float         g_h1pre[B_SZ*DETER];
__device__ __nv_bfloat16 g_h1   [B_SZ*DETER];
__device__ float         g_gpre [B_SZ*3*DETER];

// ---------------- cp.async helpers ----------------
__device__ __forceinline__ void cp_async16(void* smem, const void* gmem)
{
    unsigned int s = (unsigned int)__cvta_generic_to_shared(smem);
    asm volatile("cp.async.cg.shared.global [%0], [%1], 16;\n" :: "r"(s), "l"(gmem));
}
__device__ __forceinline__ void cp_commit() { asm volatile("cp.async.commit_group;\n"); }
template<int N> __device__ __forceinline__ void cp_wait() { asm volatile("cp.async.wait_group %0;\n" :: "n"(N)); }

// =====================================================================
// ONE conversion kernel for all weights + activations (R8-proven).
// =====================================================================
#define CB_W0    4096
#define CB_W1    (CB_W0 + 1024)
#define CB_W2    (CB_W1 + 128)
#define CB_HW0   (CB_W2 + 14336)
#define CB_HW1   (CB_HW0 + 2048)
#define CB_GW    (CB_HW1 + 6144)
#define CB_DET   (CB_GW + 4096)
#define CB_STO   (CB_DET + 1024)
#define CB_ACT   (CB_STO + 128)

__global__ void __launch_bounds__(256)
convall_kernel(const float* __restrict__ w0, const float* __restrict__ w1,
               const float* __restrict__ w2, const float* __restrict__ hw0,
               const float* __restrict__ hw1, const float* __restrict__ gw,
               const float* __restrict__ deter, const float* __restrict__ stoch,
               const float* __restrict__ action,
               __nv_bfloat16* o_w0, __nv_bfloat16* o_w1, __nv_bfloat16* o_w2,
               __nv_bfloat16* o_hw0, __nv_bfloat16* o_hw1, __nv_bfloat16* o_gw,
               __nv_bfloat16* o_det, __nv_bfloat16* o_sto, __nv_bfloat16* o_act)
{
    const int b = blockIdx.x;
    const float* src; __nv_bfloat16* dst; int base; bool is_act = false;
    if      (b < CB_W0)  { src = w0;    dst = o_w0;  base = b; }
    else if (b < CB_W1)  { src = w1;    dst = o_w1;  base = b - CB_W0; }
    else if (b < CB_W2)  { src = w2;    dst = o_w2;  base = b - CB_W1; }
    else if (b < CB_HW0) { src = hw0;   dst = o_hw0; base = b - CB_W2; }
    else if (b < CB_HW1) { src = hw1;   dst = o_hw1; base = b - CB_HW0; }
    else if (b < CB_GW)  { src = gw;    dst = o_gw;  base = b - CB_HW1; }
    else if (b < CB_DET) { src = deter; dst = o_det; base = b - CB_GW; }
    else if (b < CB_STO) { src = stoch; dst = o_sto; base = b - CB_DET; }
    else                 { src = action; dst = o_act; base = b - CB_STO; is_act = true; }

    int i = base * 256 + threadIdx.x;
    float4 t = ((const float4*)src)[i];
    if (is_act) {
        t.x /= fmaxf(fabsf(t.x), 1.0f);
        t.y /= fmaxf(fabsf(t.y), 1.0f);
        t.z /= fmaxf(fabsf(t.z), 1.0f);
        t.w /= fmaxf(fabsf(t.w), 1.0f);
    }
    ((__nv_bfloat162*)dst)[2*i]   = __floats2bfloat162_rn(t.x, t.y);
    ((__nv_bfloat162*)dst)[2*i+1] = __floats2bfloat162_rn(t.z, t.w);
}

// =====================================================================
// 3-stage, BK=64 bf16 GEMM (wmma + cp.async), split-A capable, BM=128.
// ONE __syncthreads per k-chunk (3-stage rotation makes write/read/in-flight
// buffers pairwise distinct). Dynamic smem: 3 x (A 18432B + B 17408B) = 105KB.
// =====================================================================
#define GB_SA_ELEMS (128 * 72)      /* A stage: [128][64+8] */
#define GB_SB_ELEMS (64 * 136)      /* B stage: [64][128+8] */
#define GB_SMEM (3 * 2 * (GB_SA_ELEMS + GB_SB_ELEMS))   /* 107520 B */

__global__ void __launch_bounds__(256)
gemm_bd3_kernel(const __nv_bfloat16* __restrict__ A0, int lda0, long long a0_zs,
                const __nv_bfloat16* __restrict__ A1, int lda1, int k0, int K,
                const __nv_bfloat16* __restrict__ Bp, int ldb, long long b_zs,
                float* __restrict__ C, int ldc, long long c_zs)
{
    extern __shared__ __nv_bfloat16 dsm[];
    __nv_bfloat16* sA = dsm;                      // 3 stages of [128][72]
    __nv_bfloat16* sB = dsm + 3 * GB_SA_ELEMS;    // 3 stages of [64][136]

    const int z = blockIdx.z;
    const __nv_bfloat16* A0z = A0 + (long long)z * a0_zs;
    const __nv_bfloat16* Bz  = Bp + (long long)z * b_zs;
    float* Cz = C + (long long)z * c_zs;

    const int tile_m = blockIdx.x * 128;
    const int tile_n = blockIdx.y * 128;
    const int tid  = threadIdx.x;
    const int warp = tid >> 5;
    const int wm   = warp & 1;    // 2 warps along M (64 rows each)
    const int wn   = warp >> 1;   // 4 warps along N (32 cols each)

    auto issue = [&](int ck, int stg) {
        const int kk = ck * 64;
        const __nv_bfloat16* Asrc; int lda, kcol;
        if (kk < k0) { Asrc = A0z; lda = lda0; kcol = kk; }
        else         { Asrc = A1;  lda = lda1; kcol = kk - k0; }
        __nv_bfloat16* a = sA + stg * GB_SA_ELEMS;
#pragma unroll
        for (int i = 0; i < 4; i++) {             // A: 128 x 64 = 1024 x 16B
            int idx = tid + 256 * i;
            int r = idx >> 3, u = (idx & 7) * 8;
            cp_async16(a + r * 72 + u,
                       Asrc + (long long)(tile_m + r) * lda + kcol + u);
        }
        __nv_bfloat16* bp = sB + stg * GB_SB_ELEMS;
#pragma unroll
        for (int i = 0; i < 4; i++) {             // B: 64 x 128 = 1024 x 16B
            int idx = tid + 256 * i;
            int r = idx >> 4, c = (idx & 15) * 8;
            cp_async16(bp + r * 136 + c,
                       Bz + (long long)(kk + r) * ldb + tile_n + c);
        }
    };

    wmma::fragment<wmma::accumulator, 16, 16, 16, float> acc[4][2];
#pragma unroll
    for (int i = 0; i < 4; i++)
#pragma unroll
        for (int j = 0; j < 2; j++) wmma::fill_fragment(acc[i][j], 0.0f);

    const int nck = K / 64;
    issue(0, 0); cp_commit();
    if (nck > 1) { issue(1, 1); cp_commit(); }

    for (int c = 0; c < nck; c++) {
        if (c + 1 < nck) cp_wait<1>(); else cp_wait<0>();
        __syncthreads();                          // the ONLY barrier per chunk
        const int stg = c % 3;
        const __nv_bfloat16* a = sA + stg * GB_SA_ELEMS;
        const __nv_bfloat16* bp = sB + stg * GB_SB_ELEMS;
#pragma unroll
        for (int kf = 0; kf < 4; kf++) {
            wmma::fragment<wmma::matrix_a, 16, 16, 16, __nv_bfloat16, wmma::row_major> af[4];
            wmma::fragment<wmma::matrix_b, 16, 16, 16, __nv_bfloat16, wmma::row_major> bf[2];
#pragma unroll
            for (int i = 0; i < 4; i++)
                wmma::load_matrix_sync(af[i], a + (wm * 64 + i * 16) * 72 + kf * 16, 72);
#pragma unroll
            for (int j = 0; j < 2; j++)
                wmma::load_matrix_sync(bf[j], bp + (kf * 16) * 136 + wn * 32 + j * 16, 136);
#pragma unroll
            for (int i = 0; i < 4; i++)
#pragma unroll
                for (int j = 0; j < 2; j++)
                    wmma::mma_sync(acc[i][j], af[i], bf[j], acc[i][j]);
        }
        if (c + 2 < nck) { issue(c + 2, (c + 2) % 3); cp_commit(); }
    }

#pragma unroll
    for (int i = 0; i < 4; i++)
#pragma unroll
        for (int j = 0; j < 2; j++) {
            float* cp = Cz + (long long)(tile_m + wm * 64 + i * 16) * ldc
                           + tile_n + wn * 32 + j * 16;
            wmma::store_matrix_sync(cp, acc[i][j], ldc, wmma::mem_row_major);
        }
}

// =====================================================================
// Fused 3-branch input GEMM (wmma, BM=64, BN=128, BK=32); grid (B/64, 24)
// =====================================================================
__global__ void __launch_bounds__(256)
gemm_branch_kernel(const __nv_bfloat16* __restrict__ Ad,
                   const __nv_bfloat16* __restrict__ As,
                   const __nv_bfloat16* __restrict__ Aa,
                   const __nv_bfloat16* __restrict__ W0p,
                   const __nv_bfloat16* __restrict__ W1p,
                   const __nv_bfloat16* __restrict__ W2p,
                   float* __restrict__ Y)
{
    constexpr int BM = 64, BN = 128, BK = 32;
    constexpr int FM = 2;
    __shared__ __nv_bfloat16 sA[2][BM][BK + 8];
    __shared__ __nv_bfloat16 sB[2][BK][BN + 8];

    const int br = blockIdx.y >> 3;
    const int tile_n_local = (blockIdx.y & 7) * BN;
    const __nv_bfloat16* A = (br == 0) ? Ad : (br == 1) ? As : Aa;
    const __nv_bfloat16* W = (br == 0) ? W0p : (br == 1) ? W1p : W2p;
    const int K = (br == 0) ? DETER : (br == 1) ? STOCH : ACT;
    const int lda = K;

    const int tile_m = blockIdx.x * BM;
    const int tid  = threadIdx.x;
    const int warp = tid >> 5;
    const int wm   = warp & 1;
    const int wn   = warp >> 1;

    auto issue = [&](int kk, int stg) {
        {
            int r = tid >> 2, v = tid & 3;
            cp_async16(&sA[stg][r][v * 8], A + (long long)(tile_m + r) * lda + kk + v * 8);
        }
#pragma unroll
        for (int i = 0; i < 2; i++) {
            int idx = tid + 256 * i;
            int r = idx >> 4, c = (idx & 15) * 8;
            cp_async16(&sB[stg][r][c], W + (long long)(kk + r) * HID + tile_n_local + c);
        }
    };

    wmma::fragment<wmma::accumulator, 16, 16, 16, float> acc[FM][2];
#pragma unroll
    for (int i = 0; i < FM; i++)
#pragma unroll
        for (int j = 0; j < 2; j++) wmma::fill_fragment(acc[i][j], 0.0f);

    const int nsteps = K / BK;
    issue(0, 0); cp_commit();

    for (int s = 0; s < nsteps; s++) {
        if (s + 1 < nsteps) { issue((s + 1) * BK, (s + 1) & 1); cp_commit(); cp_wait<1>(); }
        else                { cp_wait<0>(); }
        __syncthreads();
        const int stg = s & 1;
#pragma unroll
        for (int kf = 0; kf < 2; kf++) {
            wmma::fragment<wmma::matrix_a, 16, 16, 16, __nv_bfloat16, wmma::row_major> af[FM];
            wmma::fragment<wmma::matrix_b, 16, 16, 16, __nv_bfloat16, wmma::row_major> bf[2];
#pragma unroll
            for (int i = 0; i < FM; i++)
                wmma::load_matrix_sync(af[i], &sA[stg][wm * 32 + i * 16][kf * 16], BK + 8);
#pragma unroll
            for (int j = 0; j < 2; j++)
                wmma::load_matrix_sync(bf[j], &sB[stg][kf * 16][wn * 32 + j * 16], BN + 8);
#pragma unroll
            for (int i = 0; i < FM; i++)
#pragma unroll
                for (int j = 0; j < 2; j++)
                    wmma::mma_sync(acc[i][j], af[i], bf[j], acc[i][j]);
        }
        __syncthreads();
    }
#pragma unroll
    for (int i = 0; i < FM; i++)
#pragma unroll
        for (int j = 0; j < 2; j++) {
            float* cp = Y + (long long)(tile_m + wm * 32 + i * 16) * (3 * HID)
                          + br * HID + tile_n_local + wn * 32 + j * 16;
            wmma::store_matrix_sync(cp, acc[i][j], 3 * HID, wmma::mem_row_major);
        }
}

// ---------------- fused bias + RMSNorm + gain + SiLU -> bf16 ----------------
__global__ void __launch_bounds__(256)
norm_silu_kernel(const float* __restrict__ Y, int ldy,
                 const float* __restrict__ bias, const float* __restrict__ gain,
                 __nv_bfloat16* __restrict__ outp, int ldo, int W)
{
    const int row = blockIdx.x;
    const int tid = threadIdx.x;
    const int nv  = W >> 10;
    const float* yr = Y + (long long)row * ldy;

    float v[16];
    float ss = 0.0f;
#pragma unroll
    for (int i = 0; i < 4; i++) {
        if (i >= nv) break;
        int c = (tid + (i << 8)) << 2;
        float4 t  = *(const float4*)(yr + c);
        float4 bb = *(const float4*)(bias + c);
        t.x += bb.x; t.y += bb.y; t.z += bb.z; t.w += bb.w;
        v[4*i+0]=t.x; v[4*i+1]=t.y; v[4*i+2]=t.z; v[4*i+3]=t.w;
        ss += t.x*t.x + t.y*t.y + t.z*t.z + t.w*t.w;
    }
#pragma unroll
    for (int o = 16; o > 0; o >>= 1) ss += __shfl_xor_sync(0xffffffffu, ss, o);
    __shared__ float red[8];
    if ((tid & 31) == 0) red[tid >> 5] = ss;
    __syncthreads();
    float tot = 0.0f;
#pragma unroll
    for (int i = 0; i < 8; i++) tot += red[i];
    const float scale = rsqrtf(tot / (float)W + 1e-4f);

    __nv_bfloat16* orow = outp + (long long)row * ldo;
#pragma unroll
    for (int i = 0; i < 4; i++) {
        if (i >= nv) break;
        int c = (tid + (i << 8)) << 2;
        float4 gg = *(const float4*)(gain + c);
        float t0 = v[4*i+0]*scale*gg.x, t1 = v[4*i+1]*scale*gg.y;
        float t2 = v[4*i+2]*scale*gg.z, t3 = v[4*i+3]*scale*gg.w;
        float s0 = t0 / (1.0f + expf(-t0));
        float s1 = t1 / (1.0f + expf(-t1));
        float s2 = t2 / (1.0f + expf(-t2));
        float s3 = t3 / (1.0f + expf(-t3));
        *((__nv_bfloat162*)(orow + c))     = __floats2bfloat162_rn(s0, s1);
        *((__nv_bfloat162*)(orow + c) + 1) = __floats2bfloat162_rn(s2, s3);
    }
}

// 3-branch norm (W = HID), grid (B, 3)
__global__ void __launch_bounds__(256)
norm3_kernel(const float* __restrict__ Y,
             const float* __restrict__ b0, const float* __restrict__ g0,
             const float* __restrict__ b1, const float* __restrict__ g1,
             const float* __restrict__ b2, const float* __restrict__ g2,
             __nv_bfloat16* __restrict__ outp)
{
    const int row = blockIdx.x;
    const int br  = blockIdx.y;
    const int tid = threadIdx.x;
    const float* bias = (br == 0) ? b0 : (br == 1) ? b1 : b2;
    const float* gain = (br == 0) ? g0 : (br == 1) ? g1 : g2;
    const float* yr = Y + (long long)row * (3 * HID) + br * HID;

    int c = tid << 2;
    float4 t  = *(const float4*)(yr + c);
    float4 bb = *(const float4*)(bias + c);
    t.x += bb.x; t.y += bb.y; t.z += bb.z; t.w += bb.w;
    float ss = t.x*t.x + t.y*t.y + t.z*t.z + t.w*t.w;
#pragma unroll
    for (int o = 16; o > 0; o >>= 1) ss += __shfl_xor_sync(0xffffffffu, ss, o);
    __shared__ float red[8];
    if ((tid & 31) == 0) red[tid >> 5] = ss;
    __syncthreads();
    float tot = 0.0f;
#pragma unroll
    for (int i = 0; i < 8; i++) tot += red[i];
    const float scale = rsqrtf(tot / (float)HID + 1e-4f);

    float4 gg = *(const float4*)(gain + c);
    float t0 = t.x*scale*gg.x, t1 = t.y*scale*gg.y;
    float t2 = t.z*scale*gg.z, t3 = t.w*scale*gg.w;
    float s0 = t0 / (1.0f + expf(-t0));
    float s1 = t1 / (1.0f + expf(-t1));
    float s2 = t2 / (1.0f + expf(-t2));
    float s3 = t3 / (1.0f + expf(-t3));
    __nv_bfloat16* orow = outp + (long long)row * (3 * HID) + br * HID;
    *((__nv_bfloat162*)(orow + c))     = __floats2bfloat162_rn(s0, s1);
    *((__nv_bfloat162*)(orow + c) + 1) = __floats2bfloat162_rn(s2, s3);
}

// ---------------- GRU gate epilogue ----------------
__global__ void __launch_bounds__(256)
gru_kernel(const float* __restrict__ gpre, const float* __restrict__ gb,
           const float* __restrict__ deter, float* __restrict__ out)
{
    int i = blockIdx.x * blockDim.x + threadIdx.x;
    int b  = i >> 10;
    int jv = i & 1023;
    int j  = jv << 2;
    int blk = j >> 9;
    int o   = j & 511;
    const float* gp  = gpre + (long long)b * (3 * DETER) + blk * (3 * DPB);
    const float* gbp = gb + blk * (3 * DPB);
    float4 r4 = *(const float4*)(gp + o);
    float4 rb = *(const float4*)(gbp + o);
    float4 c4 = *(const float4*)(gp + DPB + o);
    float4 cb = *(const float4*)(gbp + DPB + o);
    float4 u4 = *(const float4*)(gp + 2 * DPB + o);
    float4 ub = *(const float4*)(gbp + 2 * DPB + o);
    float4 d4 = *(const float4*)(deter + (long long)b * DETER + j);

    float4 res;
    {
        float rr = 1.0f / (1.0f + expf(-(r4.x + rb.x)));
        float cc = tanhf(rr * (c4.x + cb.x));
        float uu = 1.0f / (1.0f + expf(-(u4.x + ub.x - 1.0f)));
        res.x = uu * cc + (1.0f - uu) * d4.x;
    }
    {
        float rr = 1.0f / (1.0f + expf(-(r4.y + rb.y)));
        float cc = tanhf(rr * (c4.y + cb.y));
        float uu = 1.0f / (1.0f + expf(-(u4.y + ub.y - 1.0f)));
        res.y = uu * cc + (1.0f - uu) * d4.y;
    }
    {
        float rr = 1.0f / (1.0f + expf(-(r4.z + rb.z)));
        float cc = tanhf(rr * (c4.z + cb.z));
        float uu = 1.0f / (1.0f + expf(-(u4.z + ub.z - 1.0f)));
        res.z = uu * cc + (1.0f - uu) * d4.z;
    }
    {
        float rr = 1.0f / (1.0f + expf(-(r4.w + rb.w)));
        float cc = tanhf(rr * (c4.w + cb.w));
        float uu = 1.0f / (1.0f + expf(-(u4.w + ub.w - 1.0f)));
        res.w = uu * cc + (1.0f - uu) * d4.w;
    }
    *(float4*)(out + (long long)b * DETER + j) = res;
}

// ---------------- host ----------------
extern "C" void kernel_launch(void* const* d_in, const int* in_sizes, int n_in,
                              void* d_out, int out_size)
{
    (void)in_sizes; (void)n_in; (void)out_size;
    const float* stoch  = (const float*)d_in[0];
    const float* deter  = (const float*)d_in[1];
    const float* action = (const float*)d_in[2];
    const float* w0 = (const float*)d_in[3];
    const float* b0 = (const float*)d_in[4];
    const float* g0 = (const float*)d_in[5];
    const float* w1 = (const float*)d_in[6];
    const float* b1 = (const float*)d_in[7];
    const float* g1 = (const float*)d_in[8];
    const float* w2 = (const float*)d_in[9];
    const float* b2 = (const float*)d_in[10];
    const float* g2 = (const float*)d_in[11];
    const float* hw0 = (const float*)d_in[12];
    const float* hb0 = (const float*)d_in[13];
    const float* hg0 = (const float*)d_in[14];
    const float* hw1 = (const float*)d_in[15];
    const float* hb1 = (const float*)d_in[16];
    const float* hg1 = (const float*)d_in[17];
    const float* gw  = (const float*)d_in[18];
    const float* gb  = (const float*)d_in[19];
    float* out = (float*)d_out;

    void *p_w0, *p_w1, *p_w2, *p_hw0, *p_hw1, *p_gw;
    void *p_deter, *p_stoch, *p_act, *p_y, *p_x, *p_h0pre, *p_h0, *p_h1pre, *p_h1, *p_gpre;
    cudaGetSymbolAddress(&p_w0, g_w0);
    cudaGetSymbolAddress(&p_w1, g_w1);
    cudaGetSymbolAddress(&p_w2, g_w2);
    cudaGetSymbolAddress(&p_hw0, g_hw0);
    cudaGetSymbolAddress(&p_hw1, g_hw1);
    cudaGetSymbolAddress(&p_gw, g_gw);
    cudaGetSymbolAddress(&p_deter, g_deter_bf);
    cudaGetSymbolAddress(&p_stoch, g_stoch_bf);
    cudaGetSymbolAddress(&p_act, g_act_bf);
    cudaGetSymbolAddress(&p_y, g_y);
    cudaGetSymbolAddress(&p_x, g_x);
    cudaGetSymbolAddress(&p_h0pre, g_h0pre);
    cudaGetSymbolAddress(&p_h0, g_h0);
    cudaGetSymbolAddress(&p_h1pre, g_h1pre);
    cudaGetSymbolAddress(&p_h1, g_h1);
    cudaGetSymbolAddress(&p_gpre, g_gpre);

    cudaFuncSetAttribute(gemm_bd3_kernel, cudaFuncAttributeMaxDynamicSharedMemorySize, GB_SMEM);

    // --- single fused conversion launch ---
    convall_kernel<<<CB_ACT, 256>>>(w0, w1, w2, hw0, hw1, gw, deter, stoch, action,
                                    (__nv_bfloat16*)p_w0, (__nv_bfloat16*)p_w1,
                                    (__nv_bfloat16*)p_w2, (__nv_bfloat16*)p_hw0,
                                    (__nv_bfloat16*)p_hw1, (__nv_bfloat16*)p_gw,
                                    (__nv_bfloat16*)p_deter, (__nv_bfloat16*)p_stoch,
                                    (__nv_bfloat16*)p_act);

    // --- fused branch GEMMs ---
    {
        dim3 grid(B_SZ / 64, 24, 1);
        gemm_branch_kernel<<<grid, 256>>>((const __nv_bfloat16*)p_deter,
                                          (const __nv_bfloat16*)p_stoch,
                                          (const __nv_bfloat16*)p_act,
                                          (const __nv_bfloat16*)p_w0,
                                          (const __nv_bfloat16*)p_w1,
                                          (const __nv_bfloat16*)p_w2,
                                          (float*)p_y);
    }
    // branch norms -> x (bf16, [B, 3*HID])
    {
        dim3 grid(B_SZ, 3, 1);
        norm3_kernel<<<grid, 256>>>((const float*)p_y, b0, g0, b1, g1, b2, g2,
                                    (__nv_bfloat16*)p_x);
    }

    // --- hidden block layer 0: split A = [deter_block(512) | x(3072)] ---
    {
        dim3 grid(B_SZ / 128, DPB / 128, NBLK);
        gemm_bd3_kernel<<<grid, 256, GB_SMEM>>>((const __nv_bfloat16*)p_deter, DETER, DPB,
                                                (const __nv_bfloat16*)p_x, 3 * HID, DPB, INCH0,
                                                (const __nv_bfloat16*)p_hw0, DPB, (long long)INCH0 * DPB,
                                                (float*)p_h0pre, DETER, DPB);
    }
    norm_silu_kernel<<<B_SZ, 256>>>((const float*)p_h0pre, DETER, hb0, hg0,
                                    (__nv_bfloat16*)p_h0, DETER, DETER);

    // --- hidden block layer 1 ---
    {
        dim3 grid(B_SZ / 128, DPB / 128, NBLK);
        gemm_bd3_kernel<<<grid, 256, GB_SMEM>>>((const __nv_bfloat16*)p_h0, DETER, DPB,
                                                nullptr, 0, DPB, DPB,
                                                (const __nv_bfloat16*)p_hw1, DPB, (long long)DPB * DPB,
                                                (float*)p_h1pre, DETER, DPB);
    }
    norm_silu_kernel<<<B_SZ, 256>>>((const float*)p_h1pre, DETER, hb1, hg1,
                                    (__nv_bfloat16*)p_h1, DETER, DETER);

    // --- gate GEMM: per block [1024,512] @ [512,1536] ---
    {
        dim3 grid(B_SZ / 128, (3 * DPB) / 128, NBLK);
        gemm_bd3_kernel<<<grid, 256, GB_SMEM>>>((const __nv_bfloat16*)p_h1, DETER, DPB,
                                                nullptr, 0, DPB, DPB,
                                                (const __nv_bfloat16*)p_gw, 3 * DPB, (long long)DPB * 3 * DPB,
                                                (float*)p_gpre, 3 * DETER, 3 * DPB);
    }

    // --- GRU epilogue ---
    {
        int nvec = (B_SZ * DETER) >> 2;
        gru_kernel<<<nvec / 256, 256>>>((const float*)p_gpre, gb, deter, out);
    }
}